// round 4
// baseline (speedup 1.0000x reference)
#include <cuda_runtime.h>
#include <cuda_bf16.h>
#include <cstdint>

// LearnableTopP: per row of 1024 fp32 softmax probs:
//   descending stable sort (ties -> smaller original index first),
//   inclusive cumsum, mask = cumsum <= sigmoid(threshold[s % 16]),
//   padded_idx = mask ? sorted_index : -1, counts = popcount(mask).
// Outputs are written as FLOAT32 (harness canonical output dtype):
//   [ padded_idx (B*H*S*S floats) | counts (B*H*S floats) ]
//
// One warp per row. 32 elements per lane in registers as packed u64 keys:
//   key = (u64(float_bits) << 10) | (1023 - idx)
// (softmax values >= 0, so fp32 bits compare like the floats; low bits give
// the stable tie-break of jnp.argsort(-x): equal values -> smaller idx first.)
// Full 1024-element bitonic network, DESCENDING over position i = lane*32 + r:
//   - j < 32  : partner is register r ^ j in the same lane (40 phases)
//   - j >= 32 : partner is lane ^ (j>>5), same register slot, via shfl (15 phases)

using u64 = unsigned long long;

static __device__ __forceinline__ u64 umax64(u64 a, u64 b) { return a > b ? a : b; }
static __device__ __forceinline__ u64 umin64(u64 a, u64 b) { return a > b ? b : a; }

__global__ void __launch_bounds__(256) topp_sort_kernel(
    const float* __restrict__ atn,
    const float* __restrict__ thresholds,
    float* __restrict__ out_idx,
    float* __restrict__ out_counts)
{
    const int warp = threadIdx.x >> 5;
    const int lane = threadIdx.x & 31;
    const int row  = blockIdx.x * 8 + warp;   // 65536 rows, 8 warps/CTA

    const float* rowp = atn + (size_t)row * 1024;

    // --- load 32 contiguous elements per lane (blocked layout), pack keys ---
    u64 key[32];
    const float4* rowp4 = reinterpret_cast<const float4*>(rowp);
#pragma unroll
    for (int q = 0; q < 8; ++q) {
        float4 f = rowp4[lane * 8 + q];
        int base = (lane << 5) + (q << 2);
        key[q * 4 + 0] = ((u64)__float_as_uint(f.x) << 10) | (u64)(1023 - (base + 0));
        key[q * 4 + 1] = ((u64)__float_as_uint(f.y) << 10) | (u64)(1023 - (base + 1));
        key[q * 4 + 2] = ((u64)__float_as_uint(f.z) << 10) | (u64)(1023 - (base + 2));
        key[q * 4 + 3] = ((u64)__float_as_uint(f.w) << 10) | (u64)(1023 - (base + 3));
    }

    // --- bitonic sort, descending over global positions i = lane*32 + r ---
#pragma unroll
    for (int k = 2; k <= 1024; k <<= 1) {
#pragma unroll
        for (int j = k >> 1; j > 0; j >>= 1) {
            if (j >= 32) {
                // cross-lane phase: partner lane = lane ^ (j>>5), same r slot
                const int jl = j >> 5;
                const bool isLower = ((lane & jl) == 0);
                const bool descBlk = ((lane & (k >> 5)) == 0);   // (i & k) == 0
                const bool keepMax = (descBlk == isLower);
#pragma unroll
                for (int r = 0; r < 32; ++r) {
                    u64 other = __shfl_xor_sync(0xffffffffu, key[r], jl);
                    u64 mx = umax64(key[r], other);
                    u64 mn = umin64(key[r], other);
                    key[r] = keepMax ? mx : mn;
                }
            } else {
                // intra-lane phase: partner register r ^ j
#pragma unroll
                for (int r = 0; r < 32; ++r) {
                    if ((r & j) == 0) {
                        const int lo = r, hi = r | j;
                        bool descBlk;
                        if (k >= 32) descBlk = ((lane & (k >> 5)) == 0); // lane bits of (i & k)
                        else         descBlk = ((lo & k) == 0);          // compile-time
                        u64 a = key[lo], b = key[hi];
                        u64 mx = umax64(a, b);
                        u64 mn = umin64(a, b);
                        key[lo] = descBlk ? mx : mn;
                        key[hi] = descBlk ? mn : mx;
                    }
                }
            }
        }
    }

    // --- threshold: row (h*S + s) uses threshold[(h*S+s) % 16] == s % 16;
    //     row & 15 computes the same residue since H*S and S are mult. of 16 ---
    float t   = thresholds[row & 15];
    float thr = 1.0f / (1.0f + expf(-t));

    // --- cumsum: lane-local total, warp exclusive scan, then streamed prefix ---
    float tot = 0.0f;
#pragma unroll
    for (int r = 0; r < 32; ++r)
        tot += __uint_as_float((unsigned)(key[r] >> 10));

    float scan = tot;
#pragma unroll
    for (int d = 1; d < 32; d <<= 1) {
        float n = __shfl_up_sync(0xffffffffu, scan, d);
        if (lane >= d) scan += n;
    }
    float run = scan - tot;   // exclusive offset for this lane

    // --- emit padded indices (as float) + count ---
    float4* orow = reinterpret_cast<float4*>(out_idx + (size_t)row * 1024);
    int cnt = 0;
    float ov[4];
#pragma unroll
    for (int r = 0; r < 32; ++r) {
        run += __uint_as_float((unsigned)(key[r] >> 10));   // inclusive cumsum
        bool sel = (run <= thr);
        int id = 1023 - (int)(key[r] & 1023ULL);
        ov[r & 3] = sel ? (float)id : -1.0f;
        cnt += sel ? 1 : 0;
        if ((r & 3) == 3)
            orow[lane * 8 + (r >> 2)] = make_float4(ov[0], ov[1], ov[2], ov[3]);
    }

    if (out_counts) {
#pragma unroll
        for (int d = 16; d > 0; d >>= 1)
            cnt += __shfl_xor_sync(0xffffffffu, cnt, d);
        if (lane == 0) out_counts[row] = (float)cnt;
    }
}

extern "C" void kernel_launch(void* const* d_in, const int* in_sizes, int n_in,
                              void* d_out, int out_size)
{
    const float* atn = (const float*)d_in[0];
    const float* thr = (const float*)d_in[1];
    (void)n_in;

    const int S    = 1024;
    const int rows = in_sizes[0] / S;                 // 65536
    long long padded = (long long)rows * S;           // 67,108,864

    float* out    = (float*)d_out;
    float* counts = ((long long)out_size >= padded + rows) ? (out + padded) : nullptr;

    dim3 block(256);                                  // 8 warps = 8 rows per CTA
    dim3 grid(rows / 8);
    topp_sort_kernel<<<grid, block>>>(atn, thr, out, counts);
}

// round 5
// speedup vs baseline: 1.7146x; 1.7146x over previous
#include <cuda_runtime.h>
#include <cuda_bf16.h>
#include <cstdint>

// LearnableTopP: per row of 1024 fp32 softmax probs:
//   descending stable sort (ties -> smaller original index first),
//   inclusive cumsum, mask = cumsum <= sigmoid(threshold[s % 16]),
//   padded_idx = mask ? sorted_index : -1, counts = popcount(mask).
// Outputs as FLOAT32: [ padded_idx (rows*1024) | counts (rows) ].
//
// One warp per row; 32 packed u64 keys per lane:
//   key = (u64(float_bits) << 10) | (1023 - idx)
// Keys are globally unique (idx embedded) -> a single compare predicate can
// route both sides of every compare-exchange exactly (no tie hazard).
// CAS form: q = (a > b) == dir;  A = q?a:b;  B = q?b:a;
//   -> 2 ISETP(.EX) + 1 PLOP + 4 SEL (vs max64+min64+select = ~10 ops).

using u64 = unsigned long long;

static __device__ __forceinline__ void cas(u64 &A, u64 &B, bool dir) {
    u64 a = A, b = B;
    bool q = (a > b) == dir;   // dir=true: A gets the larger key
    A = q ? a : b;
    B = q ? b : a;
}

__global__ void __launch_bounds__(256) topp_sort_kernel(
    const float* __restrict__ atn,
    const float* __restrict__ thresholds,
    float* __restrict__ out_idx,
    float* __restrict__ out_counts)
{
    const int warp = threadIdx.x >> 5;
    const int lane = threadIdx.x & 31;
    const int row  = blockIdx.x * 8 + warp;   // 65536 rows, 8 warps/CTA

    const float* rowp = atn + (size_t)row * 1024;

    // --- load 32 contiguous elements per lane, pack keys ---
    u64 key[32];
    const float4* rowp4 = reinterpret_cast<const float4*>(rowp);
#pragma unroll
    for (int q = 0; q < 8; ++q) {
        float4 f = rowp4[lane * 8 + q];
        int base = (lane << 5) + (q << 2);
        key[q * 4 + 0] = ((u64)__float_as_uint(f.x) << 10) | (u64)(1023 - (base + 0));
        key[q * 4 + 1] = ((u64)__float_as_uint(f.y) << 10) | (u64)(1023 - (base + 1));
        key[q * 4 + 2] = ((u64)__float_as_uint(f.z) << 10) | (u64)(1023 - (base + 2));
        key[q * 4 + 3] = ((u64)__float_as_uint(f.w) << 10) | (u64)(1023 - (base + 3));
    }

    // --- bitonic sort, descending over global positions i = lane*32 + r ---
#pragma unroll
    for (int k = 2; k <= 1024; k <<= 1) {
#pragma unroll
        for (int j = k >> 1; j > 0; j >>= 1) {
            if (j >= 32) {
                // cross-lane phase: partner lane = lane ^ (j>>5), same r slot
                const int jl = j >> 5;
                const bool isLower = ((lane & jl) == 0);
                const bool descBlk = ((lane & (k >> 5)) == 0);   // (i & k) == 0
                const bool keepMax = (descBlk == isLower);
#pragma unroll
                for (int r = 0; r < 32; ++r) {
                    u64 mine  = key[r];
                    u64 other = __shfl_xor_sync(0xffffffffu, mine, jl);
                    bool q = (mine > other) == keepMax;
                    key[r] = q ? mine : other;
                }
            } else {
                // intra-lane phase: partner register r ^ j
#pragma unroll
                for (int r = 0; r < 32; ++r) {
                    if ((r & j) == 0) {
                        const int lo = r, hi = r | j;
                        bool descBlk;
                        if (k >= 32) descBlk = ((lane & (k >> 5)) == 0); // runtime (lane bits)
                        else         descBlk = ((lo & k) == 0);          // compile-time
                        cas(key[lo], key[hi], descBlk);
                    }
                }
            }
        }
    }

    // --- threshold: row (h*S + s) uses threshold[s % 16] == row % 16 ---
    float t   = thresholds[row & 15];
    float thr = 1.0f / (1.0f + expf(-t));

    // --- cumsum: lane-local total, warp exclusive scan, streamed prefix ---
    float tot = 0.0f;
#pragma unroll
    for (int r = 0; r < 32; ++r)
        tot += __uint_as_float((unsigned)(key[r] >> 10));

    float scan = tot;
#pragma unroll
    for (int d = 1; d < 32; d <<= 1) {
        float n = __shfl_up_sync(0xffffffffu, scan, d);
        if (lane >= d) scan += n;
    }
    float run = scan - tot;   // exclusive offset for this lane

    // --- emit padded indices (as float) + count ---
    float4* orow = reinterpret_cast<float4*>(out_idx + (size_t)row * 1024);
    int cnt = 0;
    float ov[4];
#pragma unroll
    for (int r = 0; r < 32; ++r) {
        run += __uint_as_float((unsigned)(key[r] >> 10));   // inclusive cumsum
        bool sel = (run <= thr);
        int id = 1023 - (int)(key[r] & 1023ULL);
        ov[r & 3] = sel ? (float)id : -1.0f;
        cnt += sel ? 1 : 0;
        if ((r & 3) == 3)
            orow[lane * 8 + (r >> 2)] = make_float4(ov[0], ov[1], ov[2], ov[3]);
    }

    if (out_counts) {
#pragma unroll
        for (int d = 16; d > 0; d >>= 1)
            cnt += __shfl_xor_sync(0xffffffffu, cnt, d);
        if (lane == 0) out_counts[row] = (float)cnt;
    }
}

extern "C" void kernel_launch(void* const* d_in, const int* in_sizes, int n_in,
                              void* d_out, int out_size)
{
    const float* atn = (const float*)d_in[0];
    const float* thr = (const float*)d_in[1];
    (void)n_in;

    const int S    = 1024;
    const int rows = in_sizes[0] / S;                 // 65536
    long long padded = (long long)rows * S;           // 67,108,864

    float* out    = (float*)d_out;
    float* counts = ((long long)out_size >= padded + rows) ? (out + padded) : nullptr;

    dim3 block(256);                                  // 8 warps = 8 rows per CTA
    dim3 grid(rows / 8);
    topp_sort_kernel<<<grid, block>>>(atn, thr, out, counts);
}